// round 5
// baseline (speedup 1.0000x reference)
#include <cuda_runtime.h>
#include <math.h>

#define IN_F   1024
#define OUT_F  512
#define BATCH  256

// Precomputed mask words: 0 for edge; +inf bits (even o / min rows) or
// -inf bits (odd o / max rows) for no-edge. 2 MB static scratch.
__device__ unsigned int g_mask[OUT_F * IN_F];

// ---------------------------------------------------------------------------
// Kernel A: build mask from edge_type_count + uniform_noise.
// no_edge = argmax(etc + gumbel(u)) == 1, i.e. (etc1+g1) > (etc0+g0) strictly
// (jnp.argmax ties -> first index -> 0). g(u) = -log(-log(u+eps)+eps) is
// strictly increasing in u, so when etc0==etc1 this is exactly u1>u0.
// ---------------------------------------------------------------------------
__global__ void mask_kernel(const float* __restrict__ etc,
                            const float* __restrict__ un) {
    int g = blockIdx.x * blockDim.x + threadIdx.x;   // linear (o, i)
    if (g >= OUT_F * IN_F) return;
    float2 e = ((const float2*)etc)[g];
    float2 u = ((const float2*)un)[g];
    bool no_edge;
    if (e.x == e.y) {
        no_edge = (u.y > u.x);
    } else {
        const float eps = 1e-10f;
        float g0 = -logf(-logf(u.x + eps) + eps);
        float g1 = -logf(-logf(u.y + eps) + eps);
        no_edge = (e.y + g1) > (e.x + g0);
    }
    int o = g >> 10;  // IN_F = 1024
    unsigned m = 0u;
    if (no_edge) m = (o & 1) ? 0xFF800000u : 0x7F800000u;
    g_mask[g] = m;
}

// ---------------------------------------------------------------------------
// Kernel B: masked min/max reduction.
// Block tile: 32 outputs x 32 batches. 8 warps; warp handles 4 outputs of the
// SAME parity (no intra-warp divergence on the min/max op) x 32 batches
// (lane = batch). i streamed in 64-wide chunks through shared memory.
// Masking: x | infbits -> +/-inf or NaN; FMNMX IEEE minNum/maxNum semantics
// make both transparent to the reduction. Final clamp against the identity
// offset (2 / -1) reproduces the all-no-edge case exactly.
// ---------------------------------------------------------------------------
__device__ __forceinline__ float fmin_or(float a, float xv, unsigned m) {
    return fminf(a, __int_as_float(__float_as_int(xv) | m));
}
__device__ __forceinline__ float fmax_or(float a, float xv, unsigned m) {
    return fmaxf(a, __int_as_float(__float_as_int(xv) | m));
}

__global__ __launch_bounds__(256, 1)
void reduce_kernel(const float* __restrict__ x, float* __restrict__ out) {
    __shared__ float    xs[64][33];   // x chunk, transposed [i][b], padded
    __shared__ unsigned ms[32][64];   // mask chunk [o_local][i]
    __shared__ float    sm[32][33];   // output transpose staging [o_local][b]

    const int tid  = threadIdx.x;
    const int lane = tid & 31;
    const int w    = tid >> 5;
    const int b0   = blockIdx.x << 5;
    const int o0   = blockIdx.y << 5;

    // Warp -> 4 outputs of one parity: o_local = par + 8*g4 + 2*j
    const int par = w >> 2;          // 0: even rows (min), 1: odd rows (max)
    const int g4  = w & 3;
    const int ol0 = par + (g4 << 3);
    const int ol1 = ol0 + 2;
    const int ol2 = ol0 + 4;
    const int ol3 = ol0 + 6;
    const bool isMin = (par == 0);

    float init = isMin ? __int_as_float(0x7F800000) : __int_as_float(0xFF800000);
    float acc0 = init, acc1 = init, acc2 = init, acc3 = init;

    // Loader mapping: row rl in [0,32), quarter q in [0,8)
    const int rl = tid >> 3;
    const int q  = tid & 7;
    const float*    xrow = x      + (size_t)(b0 + rl) * IN_F;
    const unsigned* mrow = g_mask + (size_t)(o0 + rl) * IN_F;

    for (int c = 0; c < 16; c++) {
        const int I0 = c << 6;

        // Stage x chunk (coalesced float4 reads, transposed smem writes)
        float4 xa = *(const float4*)(xrow + I0 + (q << 2));
        float4 xb = *(const float4*)(xrow + I0 + 32 + (q << 2));
        xs[(q<<2)+0][rl] = xa.x;  xs[(q<<2)+1][rl] = xa.y;
        xs[(q<<2)+2][rl] = xa.z;  xs[(q<<2)+3][rl] = xa.w;
        xs[32+(q<<2)+0][rl] = xb.x;  xs[32+(q<<2)+1][rl] = xb.y;
        xs[32+(q<<2)+2][rl] = xb.z;  xs[32+(q<<2)+3][rl] = xb.w;

        // Stage mask chunk (row-major, vector copies)
        uint4 ma = *(const uint4*)(mrow + I0 + (q << 2));
        uint4 mb = *(const uint4*)(mrow + I0 + 32 + (q << 2));
        *(uint4*)&ms[rl][(q<<2)]      = ma;
        *(uint4*)&ms[rl][32+(q<<2)]   = mb;

        __syncthreads();

        if (isMin) {
            #pragma unroll 16
            for (int i = 0; i < 64; i += 4) {
                float x0 = xs[i+0][lane], x1 = xs[i+1][lane];
                float x2 = xs[i+2][lane], x3 = xs[i+3][lane];
                uint4 m0 = *(const uint4*)&ms[ol0][i];
                uint4 m1 = *(const uint4*)&ms[ol1][i];
                uint4 m2 = *(const uint4*)&ms[ol2][i];
                uint4 m3 = *(const uint4*)&ms[ol3][i];
                acc0 = fmin_or(acc0, x0, m0.x); acc0 = fmin_or(acc0, x1, m0.y);
                acc0 = fmin_or(acc0, x2, m0.z); acc0 = fmin_or(acc0, x3, m0.w);
                acc1 = fmin_or(acc1, x0, m1.x); acc1 = fmin_or(acc1, x1, m1.y);
                acc1 = fmin_or(acc1, x2, m1.z); acc1 = fmin_or(acc1, x3, m1.w);
                acc2 = fmin_or(acc2, x0, m2.x); acc2 = fmin_or(acc2, x1, m2.y);
                acc2 = fmin_or(acc2, x2, m2.z); acc2 = fmin_or(acc2, x3, m2.w);
                acc3 = fmin_or(acc3, x0, m3.x); acc3 = fmin_or(acc3, x1, m3.y);
                acc3 = fmin_or(acc3, x2, m3.z); acc3 = fmin_or(acc3, x3, m3.w);
            }
        } else {
            #pragma unroll 16
            for (int i = 0; i < 64; i += 4) {
                float x0 = xs[i+0][lane], x1 = xs[i+1][lane];
                float x2 = xs[i+2][lane], x3 = xs[i+3][lane];
                uint4 m0 = *(const uint4*)&ms[ol0][i];
                uint4 m1 = *(const uint4*)&ms[ol1][i];
                uint4 m2 = *(const uint4*)&ms[ol2][i];
                uint4 m3 = *(const uint4*)&ms[ol3][i];
                acc0 = fmax_or(acc0, x0, m0.x); acc0 = fmax_or(acc0, x1, m0.y);
                acc0 = fmax_or(acc0, x2, m0.z); acc0 = fmax_or(acc0, x3, m0.w);
                acc1 = fmax_or(acc1, x0, m1.x); acc1 = fmax_or(acc1, x1, m1.y);
                acc1 = fmax_or(acc1, x2, m1.z); acc1 = fmax_or(acc1, x3, m1.w);
                acc2 = fmax_or(acc2, x0, m2.x); acc2 = fmax_or(acc2, x1, m2.y);
                acc2 = fmax_or(acc2, x2, m2.z); acc2 = fmax_or(acc2, x3, m2.w);
                acc3 = fmax_or(acc3, x0, m3.x); acc3 = fmax_or(acc3, x1, m3.y);
                acc3 = fmax_or(acc3, x2, m3.z); acc3 = fmax_or(acc3, x3, m3.w);
            }
        }
        __syncthreads();
    }

    // Final clamp reproduces the all-no-edge identity offsets exactly:
    // min rows: all-masked -> acc is +inf/NaN -> 2.0; max rows: -inf/NaN -> -1.0
    float r0, r1, r2, r3;
    if (isMin) {
        r0 = fminf(acc0, 2.0f); r1 = fminf(acc1, 2.0f);
        r2 = fminf(acc2, 2.0f); r3 = fminf(acc3, 2.0f);
    } else {
        r0 = fmaxf(acc0, -1.0f); r1 = fmaxf(acc1, -1.0f);
        r2 = fmaxf(acc2, -1.0f); r3 = fmaxf(acc3, -1.0f);
    }

    // Transpose through smem for coalesced float4 output stores
    sm[ol0][lane] = r0;  sm[ol1][lane] = r1;
    sm[ol2][lane] = r2;  sm[ol3][lane] = r3;
    __syncthreads();

    float4 v;
    v.x = sm[(q<<2)+0][rl];
    v.y = sm[(q<<2)+1][rl];
    v.z = sm[(q<<2)+2][rl];
    v.w = sm[(q<<2)+3][rl];
    *(float4*)(out + (size_t)(b0 + rl) * OUT_F + o0 + (q << 2)) = v;
}

extern "C" void kernel_launch(void* const* d_in, const int* in_sizes, int n_in,
                              void* d_out, int out_size) {
    const float* x    = (const float*)d_in[0];  // [256, 1024]
    const float* etc  = (const float*)d_in[1];  // [512, 1024, 2]
    const float* un   = (const float*)d_in[2];  // [512, 1024, 2]
    float* out = (float*)d_out;                 // [256, 512]

    mask_kernel<<<(OUT_F * IN_F + 255) / 256, 256>>>(etc, un);

    dim3 grid(BATCH / 32, OUT_F / 32);   // (8, 16) = 128 blocks
    reduce_kernel<<<grid, 256>>>(x, out);
}

// round 6
// speedup vs baseline: 1.6470x; 1.6470x over previous
#include <cuda_runtime.h>
#include <math.h>

#define IN_F   1024
#define OUT_F  512
#define BATCH  256
#define CAP    96
#define TLO    0.04f
#define THI    0.96f

// no_edge bit matrices (64 KB each)
__device__ unsigned g_bits [OUT_F * (IN_F  / 32)];  // [o][i_word]   bit = i&31
__device__ unsigned g_maskT[IN_F  * (OUT_F / 32)];  // [i][o_word]   bit = o&31

// ---------------------------------------------------------------------------
// A1: no_edge = argmax(etc + gumbel(u)) == 1, i.e. (etc1+g1) > (etc0+g0)
// strictly (argmax tie -> index 0). g(u) = -log(-log(u+eps)+eps) is strictly
// increasing, so for etc0==etc1 this is exactly u1>u0. Pack bits via ballot.
// ---------------------------------------------------------------------------
__global__ __launch_bounds__(256)
void mask_bits_kernel(const float* __restrict__ etc, const float* __restrict__ un) {
    int g = blockIdx.x * 256 + threadIdx.x;          // linear (o, i)
    float2 e = ((const float2*)etc)[g];
    float2 u = ((const float2*)un)[g];
    bool no_edge;
    if (e.x == e.y) {
        no_edge = (u.y > u.x);
    } else {
        const float eps = 1e-10f;
        float g0 = -logf(-logf(u.x + eps) + eps);
        float g1 = -logf(-logf(u.y + eps) + eps);
        no_edge = (e.y + g1) > (e.x + g0);
    }
    unsigned bm = __ballot_sync(0xFFFFFFFFu, no_edge);
    if ((threadIdx.x & 31) == 0) g_bits[g >> 5] = bm;   // g>>5 = o*32 + (i>>5)
}

// ---------------------------------------------------------------------------
// A2: 32x32 bit transpose: g_bits[o][iw] -> g_maskT[i][ow].
// 512 warps, one 32x32-bit tile each. lane reads word for o = ow*32+lane;
// ballot of bit j across lanes = transposed word for i = iw*32+j.
// ---------------------------------------------------------------------------
__global__ __launch_bounds__(256)
void transpose_bits_kernel() {
    int ww = blockIdx.x * 8 + (threadIdx.x >> 5);    // 0..511
    int lane = threadIdx.x & 31;
    int ow = ww & 15;          // 0..15  (OUT_F/32)
    int iw = ww >> 4;          // 0..31  (IN_F/32)
    unsigned w = g_bits[(ow * 32 + lane) * 32 + iw];
    #pragma unroll
    for (int j = 0; j < 32; j++) {
        unsigned tw = __ballot_sync(0xFFFFFFFFu, (w >> j) & 1u);
        if (lane == j) g_maskT[(iw * 32 + j) * 16 + ow] = tw;
    }
}

// ---------------------------------------------------------------------------
// B: one block per batch. Candidate filtering: the min over ~512 unmasked
// uniform[0,1] values is < TLO with prob 1-8e-10; symmetric for max. Extract
// sub-threshold candidates into a shared list, resolve each output by
// checking its mask bit per candidate (broadcast L1-hit LDG of maskT word).
// Deterministic fallback full scan if no unmasked candidate / list overflow.
// Clamp to the identity offsets (2 / -1) handles all-no-edge rows exactly.
// ---------------------------------------------------------------------------
__global__ __launch_bounds__(256)
void select_kernel(const float* __restrict__ x, float* __restrict__ out) {
    __shared__ float xsh[IN_F];
    __shared__ float vlo[CAP]; __shared__ int ilo[CAP];
    __shared__ float vhi[CAP]; __shared__ int ihi[CAP];
    __shared__ int nlo_s, nhi_s;

    const int t = threadIdx.x;
    const int b = blockIdx.x;
    if (t == 0) { nlo_s = 0; nhi_s = 0; }
    __syncthreads();

    // Stage x row (coalesced float4), scan own 4 values for candidates
    float4 v4 = ((const float4*)(x + (size_t)b * IN_F))[t];
    ((float4*)xsh)[t] = v4;
    float vals[4] = {v4.x, v4.y, v4.z, v4.w};
    #pragma unroll
    for (int j = 0; j < 4; j++) {
        float v = vals[j];
        int   i = 4 * t + j;
        if (v < TLO) { int p = atomicAdd(&nlo_s, 1); if (p < CAP) { vlo[p] = v; ilo[p] = i; } }
        if (v > THI) { int p = atomicAdd(&nhi_s, 1); if (p < CAP) { vhi[p] = v; ihi[p] = i; } }
    }
    __syncthreads();

    const int  nlo    = min(nlo_s, CAP);
    const bool lo_ovf = (nlo_s > CAP);
    const int  nhi    = min(nhi_s, CAP);
    const bool hi_ovf = (nhi_s > CAP);

    const int oe = 2 * t;        // even output: t-norm (min)
    const int oo = 2 * t + 1;    // odd output:  t-conorm (max)
    const unsigned* __restrict__ mt = g_maskT;
    const int we = oe >> 5, be = oe & 31;
    const int wo = oo >> 5, bo = oo & 31;

    const float INF  = __int_as_float(0x7F800000);
    const float NINF = __int_as_float(0xFF800000);

    // --- min over edges of row oe ---
    float amin = INF;
    if (!lo_ovf) {
        #pragma unroll 4
        for (int c = 0; c < nlo; c++) {
            unsigned w = __ldg(&mt[ilo[c] * 16 + we]);
            if (!((w >> be) & 1u)) amin = fminf(amin, vlo[c]);
        }
    }
    if (amin == INF) {           // no unmasked candidate (or overflow): full scan
        for (int i = 0; i < IN_F; i++) {
            unsigned w = __ldg(&mt[i * 16 + we]);
            if (!((w >> be) & 1u)) amin = fminf(amin, xsh[i]);
        }
    }

    // --- max over edges of row oo ---
    float amax = NINF;
    if (!hi_ovf) {
        #pragma unroll 4
        for (int c = 0; c < nhi; c++) {
            unsigned w = __ldg(&mt[ihi[c] * 16 + wo]);
            if (!((w >> bo) & 1u)) amax = fmaxf(amax, vhi[c]);
        }
    }
    if (amax == NINF) {
        for (int i = 0; i < IN_F; i++) {
            unsigned w = __ldg(&mt[i * 16 + wo]);
            if (!((w >> bo) & 1u)) amax = fmaxf(amax, xsh[i]);
        }
    }

    // Coalesced float2 store of the (min, max) pair
    float2 r;
    r.x = fminf(amin, 2.0f);
    r.y = fmaxf(amax, -1.0f);
    *(float2*)(out + (size_t)b * OUT_F + oe) = r;
}

extern "C" void kernel_launch(void* const* d_in, const int* in_sizes, int n_in,
                              void* d_out, int out_size) {
    const float* x   = (const float*)d_in[0];  // [256, 1024]
    const float* etc = (const float*)d_in[1];  // [512, 1024, 2]
    const float* un  = (const float*)d_in[2];  // [512, 1024, 2]
    float* out = (float*)d_out;                // [256, 512]

    mask_bits_kernel<<<(OUT_F * IN_F) / 256, 256>>>(etc, un);
    transpose_bits_kernel<<<64, 256>>>();
    select_kernel<<<BATCH, 256>>>(x, out);
}

// round 7
// speedup vs baseline: 1.7146x; 1.0410x over previous
#include <cuda_runtime.h>
#include <math.h>

#define IN_F   1024
#define OUT_F  512
#define BATCH  256
#define CAP    96
#define TLO    0.04f
#define THI    0.96f

// Transposed no_edge bit matrix: [i][o_word], bit = o&31. 64 KB.
__device__ unsigned g_maskT[IN_F * (OUT_F / 32)];

// ---------------------------------------------------------------------------
// Fused mask build + bit transpose.
// no_edge = argmax(etc + gumbel(u)) == 1, i.e. (etc1+g1) > (etc0+g0) strictly
// (argmax tie -> index 0). g(u) = -log(-log(u+eps)+eps) is strictly increasing,
// so for etc0==etc1 this is exactly u1>u0; full gumbel math as fallback.
// Block = one 32(o) x 32(i) tile. Thread t: o_local = t>>3, i_local = (t&7)*4,
// loads 4 pairs (two float4 per array -> high MLP), writes 4 bit-words to
// padded smem; warps then ballot-transpose and store maskT words directly.
// ---------------------------------------------------------------------------
__device__ __forceinline__ bool no_edge_of(float e0, float e1, float u0, float u1) {
    if (e0 == e1) return u1 > u0;
    const float eps = 1e-10f;
    float g0 = -logf(-logf(u0 + eps) + eps);
    float g1 = -logf(-logf(u1 + eps) + eps);
    return (e1 + g1) > (e0 + g0);
}

__global__ __launch_bounds__(256)
void fused_mask_kernel(const float* __restrict__ etc, const float* __restrict__ un) {
    __shared__ unsigned bits[32][33];   // [i_local][o_local], padded: conflict-free

    const int t    = threadIdx.x;
    const int lane = t & 31;
    const int w    = t >> 5;
    const int ow   = blockIdx.x & 15;   // o-word index (OUT_F/32)
    const int iw   = blockIdx.x >> 4;   // i-tile index (IN_F/32)

    const int o_local = t >> 3;
    const int i_local = (t & 7) << 2;
    const size_t gpair = (size_t)(ow * 32 + o_local) * IN_F + (iw * 32 + i_local);
    const size_t f4    = gpair >> 1;    // float4 index (2 pairs per float4)

    float4 ea = ((const float4*)etc)[f4];
    float4 eb = ((const float4*)etc)[f4 + 1];
    float4 ua = ((const float4*)un)[f4];
    float4 ub = ((const float4*)un)[f4 + 1];

    bits[i_local + 0][o_local] = no_edge_of(ea.x, ea.y, ua.x, ua.y) ? 1u : 0u;
    bits[i_local + 1][o_local] = no_edge_of(ea.z, ea.w, ua.z, ua.w) ? 1u : 0u;
    bits[i_local + 2][o_local] = no_edge_of(eb.x, eb.y, ub.x, ub.y) ? 1u : 0u;
    bits[i_local + 3][o_local] = no_edge_of(eb.z, eb.w, ub.z, ub.w) ? 1u : 0u;

    __syncthreads();

    // Warp w transposes i rows w*4 .. w*4+3: ballot bit position = lane = o_local.
    #pragma unroll
    for (int r = 0; r < 4; r++) {
        const int i = (w << 2) + r;
        unsigned word = __ballot_sync(0xFFFFFFFFu, bits[i][lane] != 0u);
        if (lane == 0) g_maskT[(size_t)(iw * 32 + i) * 16 + ow] = word;
    }
}

// ---------------------------------------------------------------------------
// Select: one block per batch. The min over ~512 unmasked uniform[0,1] values
// is < TLO except with prob ~8e-10 (symmetric for max). Extract candidates
// via warp-ballot compaction, resolve each output by testing its mask bit per
// candidate (broadcast L1-hit LDG of a maskT word). Deterministic fallback
// full scan if no unmasked candidate / list overflow. Clamp to the identity
// offsets (2 / -1) handles all-no-edge rows exactly.
// ---------------------------------------------------------------------------
__global__ __launch_bounds__(256)
void select_kernel(const float* __restrict__ x, float* __restrict__ out) {
    __shared__ float xsh[IN_F];
    __shared__ float vlo[CAP]; __shared__ int ilo[CAP];
    __shared__ float vhi[CAP]; __shared__ int ihi[CAP];
    __shared__ int nlo_s, nhi_s;

    const int t    = threadIdx.x;
    const int lane = t & 31;
    const int b    = blockIdx.x;
    if (t == 0) { nlo_s = 0; nhi_s = 0; }
    __syncthreads();

    // Stage x row (coalesced float4), warp-aggregated candidate extraction
    float4 v4 = ((const float4*)(x + (size_t)b * IN_F))[t];
    ((float4*)xsh)[t] = v4;
    float vals[4] = {v4.x, v4.y, v4.z, v4.w};
    #pragma unroll
    for (int j = 0; j < 4; j++) {
        float v = vals[j];
        int   i = 4 * t + j;

        unsigned mlo = __ballot_sync(0xFFFFFFFFu, v < TLO);
        if (v < TLO) {
            int rank = __popc(mlo & ((1u << lane) - 1u));
            int base = 0;
            int lead = __ffs(mlo) - 1;
            if (lane == lead) base = atomicAdd(&nlo_s, __popc(mlo));
            base = __shfl_sync(mlo, base, lead);
            int p = base + rank;
            if (p < CAP) { vlo[p] = v; ilo[p] = i; }
        }
        unsigned mhi = __ballot_sync(0xFFFFFFFFu, v > THI);
        if (v > THI) {
            int rank = __popc(mhi & ((1u << lane) - 1u));
            int base = 0;
            int lead = __ffs(mhi) - 1;
            if (lane == lead) base = atomicAdd(&nhi_s, __popc(mhi));
            base = __shfl_sync(mhi, base, lead);
            int p = base + rank;
            if (p < CAP) { vhi[p] = v; ihi[p] = i; }
        }
    }
    __syncthreads();

    const int  nlo    = min(nlo_s, CAP);
    const bool lo_ovf = (nlo_s > CAP);
    const int  nhi    = min(nhi_s, CAP);
    const bool hi_ovf = (nhi_s > CAP);

    const int oe = 2 * t;        // even output: t-norm (min)
    const int oo = 2 * t + 1;    // odd output:  t-conorm (max)
    const unsigned* __restrict__ mt = g_maskT;
    const int we = oe >> 5, be = oe & 31;
    const int wo = oo >> 5, bo = oo & 31;

    const float INF  = __int_as_float(0x7F800000);
    const float NINF = __int_as_float(0xFF800000);

    // --- min over edges of row oe ---
    float amin = INF;
    if (!lo_ovf) {
        #pragma unroll 4
        for (int c = 0; c < nlo; c++) {
            unsigned wd = __ldg(&mt[ilo[c] * 16 + we]);
            if (!((wd >> be) & 1u)) amin = fminf(amin, vlo[c]);
        }
    }
    if (amin == INF) {           // no unmasked candidate (or overflow): full scan
        for (int i = 0; i < IN_F; i++) {
            unsigned wd = __ldg(&mt[i * 16 + we]);
            if (!((wd >> be) & 1u)) amin = fminf(amin, xsh[i]);
        }
    }

    // --- max over edges of row oo ---
    float amax = NINF;
    if (!hi_ovf) {
        #pragma unroll 4
        for (int c = 0; c < nhi; c++) {
            unsigned wd = __ldg(&mt[ihi[c] * 16 + wo]);
            if (!((wd >> bo) & 1u)) amax = fmaxf(amax, vhi[c]);
        }
    }
    if (amax == NINF) {
        for (int i = 0; i < IN_F; i++) {
            unsigned wd = __ldg(&mt[i * 16 + wo]);
            if (!((wd >> bo) & 1u)) amax = fmaxf(amax, xsh[i]);
        }
    }

    // Coalesced float2 store of the (min, max) pair
    float2 r;
    r.x = fminf(amin, 2.0f);
    r.y = fmaxf(amax, -1.0f);
    *(float2*)(out + (size_t)b * OUT_F + oe) = r;
}

extern "C" void kernel_launch(void* const* d_in, const int* in_sizes, int n_in,
                              void* d_out, int out_size) {
    const float* x   = (const float*)d_in[0];  // [256, 1024]
    const float* etc = (const float*)d_in[1];  // [512, 1024, 2]
    const float* un  = (const float*)d_in[2];  // [512, 1024, 2]
    float* out = (float*)d_out;                // [256, 512]

    fused_mask_kernel<<<(OUT_F / 32) * (IN_F / 32), 256>>>(etc, un);  // 512 blocks
    select_kernel<<<BATCH, 256>>>(x, out);
}

// round 9
// speedup vs baseline: 2.3808x; 1.3886x over previous
#include <cuda_runtime.h>
#include <math.h>

#define IN_F   1024
#define OUT_F  512
#define BATCH  256
#define CAP    96
#define TLO    0.04f
#define THI    0.96f

// Transposed no_edge bit matrix: [i][o_word], bit = o&31. 64 KB.
__device__ unsigned g_maskT[IN_F * (OUT_F / 32)];

// ---------------------------------------------------------------------------
// Fused mask build + bit transpose.
// no_edge = argmax(etc + gumbel(u)) == 1, i.e. (etc1+g1) > (etc0+g0) strictly
// (argmax tie -> index 0). g(u) = -log(-log(u+eps)+eps) is strictly
// increasing, so for etc0==etc1 this is exactly u1>u0; full gumbel math as
// the general fallback.
// Block = 32(o) x 64(i) tile (two 32x32 subtiles). Thread t: o_local = t>>3,
// i_local = (t&7)*4 in each subtile -> 8 upfront LDG.128 (MLP 8).
// ---------------------------------------------------------------------------
__device__ __forceinline__ bool no_edge_of(float e0, float e1, float u0, float u1) {
    if (e0 == e1) return u1 > u0;
    const float eps = 1e-10f;
    float g0 = -logf(-logf(u0 + eps) + eps);
    float g1 = -logf(-logf(u1 + eps) + eps);
    return (e1 + g1) > (e0 + g0);
}

__global__ __launch_bounds__(256)
void fused_mask_kernel(const float* __restrict__ etc, const float* __restrict__ un) {
    __shared__ unsigned bits[64][33];   // [i_local][o_local], padded

    const int t    = threadIdx.x;
    const int lane = t & 31;
    const int w    = t >> 5;
    const int ow   = blockIdx.x & 15;   // o-word index (OUT_F/32)
    const int it   = blockIdx.x >> 4;   // 64-wide i-tile index (IN_F/64)

    const int o_local = t >> 3;
    const int i_local = (t & 7) << 2;
    // pair index of (o, i): float4 covers 2 pairs
    const size_t gp0 = (size_t)(ow * 32 + o_local) * IN_F + (it * 64 + i_local);
    const size_t f0  = gp0 >> 1;
    const size_t f1  = f0 + 16;         // +32 i positions = +16 float4

    float4 ea0 = ((const float4*)etc)[f0];
    float4 eb0 = ((const float4*)etc)[f0 + 1];
    float4 ea1 = ((const float4*)etc)[f1];
    float4 eb1 = ((const float4*)etc)[f1 + 1];
    float4 ua0 = ((const float4*)un)[f0];
    float4 ub0 = ((const float4*)un)[f0 + 1];
    float4 ua1 = ((const float4*)un)[f1];
    float4 ub1 = ((const float4*)un)[f1 + 1];

    bits[i_local + 0][o_local]      = no_edge_of(ea0.x, ea0.y, ua0.x, ua0.y) ? 1u : 0u;
    bits[i_local + 1][o_local]      = no_edge_of(ea0.z, ea0.w, ua0.z, ua0.w) ? 1u : 0u;
    bits[i_local + 2][o_local]      = no_edge_of(eb0.x, eb0.y, ub0.x, ub0.y) ? 1u : 0u;
    bits[i_local + 3][o_local]      = no_edge_of(eb0.z, eb0.w, ub0.z, ub0.w) ? 1u : 0u;
    bits[i_local + 32 + 0][o_local] = no_edge_of(ea1.x, ea1.y, ua1.x, ua1.y) ? 1u : 0u;
    bits[i_local + 32 + 1][o_local] = no_edge_of(ea1.z, ea1.w, ua1.z, ua1.w) ? 1u : 0u;
    bits[i_local + 32 + 2][o_local] = no_edge_of(eb1.x, eb1.y, ub1.x, ub1.y) ? 1u : 0u;
    bits[i_local + 32 + 3][o_local] = no_edge_of(eb1.z, eb1.w, ub1.z, ub1.w) ? 1u : 0u;

    __syncthreads();

    // Warp w transposes i rows w*8 .. w*8+7 via ballot (bit position = lane).
    #pragma unroll
    for (int r = 0; r < 8; r++) {
        const int i = (w << 3) + r;
        unsigned word = __ballot_sync(0xFFFFFFFFu, bits[i][lane] != 0u);
        if (lane == 0) g_maskT[(size_t)(it * 64 + i) * 16 + ow] = word;
    }
}

// ---------------------------------------------------------------------------
// Select: grid (BATCH, 2). Block (b, par) resolves the 256 outputs of one
// parity for batch b; thread t -> output o = 2t+par. par 0 = t-norm (min),
// par 1 = t-conorm (max).
// The extremum over ~512 unmasked uniform[0,1] values lies below TLO (min) /
// above THI (max) except with prob ~8e-10. Extract candidates via warp-ballot
// compaction, cooperatively stage their 16-word mask rows into smem, then
// each thread scans the candidate list with pure-LDS reads (broadcast,
// conflict-free). Deterministic full-scan fallback if no unmasked candidate
// or list overflow. Clamp to identity offsets (2 / -1) handles all-no-edge
// rows exactly.
// ---------------------------------------------------------------------------
__global__ __launch_bounds__(256)
void select_kernel(const float* __restrict__ x, float* __restrict__ out) {
    __shared__ float    xsh[IN_F];
    __shared__ float    cv[CAP];
    __shared__ int      ci[CAP];
    __shared__ unsigned cm[CAP][16];
    __shared__ int      n_s;

    const int t    = threadIdx.x;
    const int lane = t & 31;
    const int b    = blockIdx.x;
    const int par  = blockIdx.y;          // 0 = min side, 1 = max side
    if (t == 0) n_s = 0;
    __syncthreads();

    // Stage x row (coalesced float4), extract this parity's candidates
    float4 v4 = ((const float4*)(x + (size_t)b * IN_F))[t];
    ((float4*)xsh)[t] = v4;
    float vals[4] = {v4.x, v4.y, v4.z, v4.w};
    #pragma unroll
    for (int j = 0; j < 4; j++) {
        float v = vals[j];
        bool  c = par ? (v > THI) : (v < TLO);
        unsigned m = __ballot_sync(0xFFFFFFFFu, c);
        if (c) {
            int rank = __popc(m & ((1u << lane) - 1u));
            int base = 0;
            int lead = __ffs(m) - 1;
            if (lane == lead) base = atomicAdd(&n_s, __popc(m));
            base = __shfl_sync(m, base, lead);
            int p = base + rank;
            if (p < CAP) { cv[p] = v; ci[p] = 4 * t + j; }
        }
    }
    __syncthreads();

    const int  n   = min(n_s, CAP);
    const bool ovf = (n_s > CAP);

    // Cooperatively stage candidate mask rows: cm[c][0..15] = maskT row ci[c]
    for (int k = t; k < n * 16; k += 256) {
        int c = k >> 4;
        cm[c][k & 15] = __ldg(&g_maskT[(size_t)ci[c] * 16 + (k & 15)]);
    }
    __syncthreads();

    const int o  = 2 * t + par;
    const int wo = o >> 5, bo = o & 31;
    const float INF  = __int_as_float(0x7F800000);
    const float NINF = __int_as_float(0xFF800000);
    const float init = par ? NINF : INF;

    float acc = init;
    if (!ovf) {
        if (par) {
            #pragma unroll 8
            for (int c = 0; c < n; c++) {
                unsigned wd = cm[c][wo];
                if (!((wd >> bo) & 1u)) acc = fmaxf(acc, cv[c]);
            }
        } else {
            #pragma unroll 8
            for (int c = 0; c < n; c++) {
                unsigned wd = cm[c][wo];
                if (!((wd >> bo) & 1u)) acc = fminf(acc, cv[c]);
            }
        }
    }
    if (acc == init) {   // no unmasked candidate (or overflow): full scan
        const unsigned* __restrict__ mt = g_maskT;
        if (par) {
            for (int i = 0; i < IN_F; i++) {
                unsigned wd = __ldg(&mt[(size_t)i * 16 + wo]);
                if (!((wd >> bo) & 1u)) acc = fmaxf(acc, xsh[i]);
            }
        } else {
            for (int i = 0; i < IN_F; i++) {
                unsigned wd = __ldg(&mt[(size_t)i * 16 + wo]);
                if (!((wd >> bo) & 1u)) acc = fminf(acc, xsh[i]);
            }
        }
    }

    float r = par ? fmaxf(acc, -1.0f) : fminf(acc, 2.0f);
    out[(size_t)b * OUT_F + o] = r;
}

extern "C" void kernel_launch(void* const* d_in, const int* in_sizes, int n_in,
                              void* d_out, int out_size) {
    const float* x   = (const float*)d_in[0];  // [256, 1024]
    const float* etc = (const float*)d_in[1];  // [512, 1024, 2]
    const float* un  = (const float*)d_in[2];  // [512, 1024, 2]
    float* out = (float*)d_out;                // [256, 512]

    fused_mask_kernel<<<(OUT_F / 32) * (IN_F / 64), 256>>>(etc, un);  // 256 blocks
    dim3 sgrid(BATCH, 2);                                             // 512 blocks
    select_kernel<<<sgrid, 256>>>(x, out);
}